// round 4
// baseline (speedup 1.0000x reference)
#include <cuda_runtime.h>
#include <math.h>

// Problem constants
#define NN    65536
#define EE    1048576
#define TPAST 20
#define TFUT  40
#define HK    48
#define H3    144
#define D3    432

#define CAP1  4096
#define CAPE  65536
#define MAX2  70000
#define SLOTS 192          // shared-mem S1 slot cap (n1 ~ Poisson(16))

#define GRID  148
#define TPB   256

// ---------------- device scratch ----------------
__device__ float g_deg[NN];
__device__ int   g_slot1[NN];
__device__ int   g_slot2[NN];
__device__ int   g_s1rows[CAP1];
__device__ float g_s1w[CAP1];
__device__ int   g_s1nodes[CAP1];
__device__ int   g_s2erow[CAPE];
__device__ int   g_s2ecol[CAPE];
__device__ float g_s2ew[CAPE];
__device__ int   g_s2nodes[MAX2];
__device__ float g_xw1[MAX2 * HK];
__device__ float g_interact[HK];
__device__ float g_target[HK];
__device__ float g_futv[HK];
__device__ float g_wdecR[3 * 3 * 48 * H3];  // decoder Whh register-slice layout
__device__ float g_wihT[H3 * D3];           // dec_Wih (432x144) transposed
__device__ int g_s1cnt, g_n1, g_s2ecnt, g_n2;

// software grid barrier state (self-resetting; generation is monotonic)
__device__ unsigned g_barArrive = 0;
__device__ unsigned g_barGen = 0;

__device__ __forceinline__ float sigmoidf(float x) { return 1.0f / (1.0f + expf(-x)); }

__device__ __forceinline__ void grid_bar() {
    __syncthreads();
    if (threadIdx.x == 0) {
        unsigned gen = atomicAdd(&g_barGen, 0u);
        __threadfence();
        unsigned t = atomicAdd(&g_barArrive, 1u);
        if (t == GRID - 1) {
            atomicExch(&g_barArrive, 0u);
            __threadfence();
            atomicAdd(&g_barGen, 1u);
        } else {
            while (atomicAdd(&g_barGen, 0u) == gen) { __nanosleep(64); }
        }
        __threadfence();
    }
    __syncthreads();
}

// ---------------- conv1d+GRU sequence (per-block, shared-memory) ----------------
__device__ void gru_seq(const float* __restrict__ xin, int T,
                        const float* __restrict__ cw, const float* __restrict__ cb,
                        const float* __restrict__ Wih, const float* __restrict__ Whh,
                        const float* __restrict__ bih, const float* __restrict__ bhh,
                        float* xs, float* xe, float* ga, float* gb, float* h) {
    int tid = threadIdx.x;
    for (int i = tid; i < 2 * T; i += TPB) xs[i] = xin[i];
    if (tid < HK) h[tid] = 0.f;
    __syncthreads();
    for (int idx = tid; idx < T * HK; idx += TPB) {
        int t = idx / HK, k = idx - t * HK;
        float acc = cb[k];
        #pragma unroll
        for (int j = 0; j < 3; j++) {
            int tt = t + j - 1;
            if (tt >= 0 && tt < T)
                acc += xs[tt * 2 + 0] * cw[(k * 2 + 0) * 3 + j]
                     + xs[tt * 2 + 1] * cw[(k * 2 + 1) * 3 + j];
        }
        xe[idx] = fmaxf(acc, 0.f);
    }
    float wi[HK], wh[HK];
    float bi = 0.f, bh = 0.f;
    if (tid < H3) {
        #pragma unroll
        for (int j = 0; j < HK; j++) { wi[j] = Wih[tid * HK + j]; wh[j] = Whh[tid * HK + j]; }
        bi = bih[tid]; bh = bhh[tid];
    }
    __syncthreads();
    for (int t = 0; t < T; t++) {
        if (tid < H3) {
            float a0 = bi, a1 = 0.f, b0 = bh, b1 = 0.f;
            const float* xt = &xe[t * HK];
            #pragma unroll
            for (int j = 0; j < HK; j += 2) {
                a0 += wi[j] * xt[j];     a1 += wi[j + 1] * xt[j + 1];
                b0 += wh[j] * h[j];      b1 += wh[j + 1] * h[j + 1];
            }
            ga[tid] = a0 + a1; gb[tid] = b0 + b1;
        }
        __syncthreads();
        float hn = 0.f;
        if (tid < HK) {
            float r = sigmoidf(ga[tid] + gb[tid]);
            float z = sigmoidf(ga[HK + tid] + gb[HK + tid]);
            float n = tanhf(ga[2 * HK + tid] + r * gb[2 * HK + tid]);
            hn = (1.f - z) * n + z * h[tid];
        }
        __syncthreads();
        if (tid < HK) h[tid] = hn;
        __syncthreads();
    }
}

// ---------------- megakernel: everything except the decoder ----------------
__global__ __launch_bounds__(TPB, 1) void k_main(
    const float* __restrict__ x,
    const float* __restrict__ past, const float* __restrict__ future,
    const int* __restrict__ ei, const float* __restrict__ ew,
    const float* __restrict__ cpw, const float* __restrict__ cpb,
    const float* __restrict__ cfw, const float* __restrict__ cfb,
    const float* __restrict__ pWih, const float* __restrict__ pWhh,
    const float* __restrict__ pbih, const float* __restrict__ pbhh,
    const float* __restrict__ fWih, const float* __restrict__ fWhh,
    const float* __restrict__ fbih, const float* __restrict__ fbhh,
    const float* __restrict__ g1w, const float* __restrict__ g1b,
    const float* __restrict__ g2w, const float* __restrict__ g2b,
    const float* __restrict__ dWih, const float* __restrict__ dWhh)
{
    __shared__ union {
        struct { float xs[2 * TFUT]; float xe[TFUT * HK]; float ga[H3]; float gb[H3]; float h[HK]; } gru;
        struct { float acc[SLOTS * HK]; float coef[SLOTS]; float xagg[HK]; } lyr;
    } sh;

    int tid = threadIdx.x;
    int gt = blockIdx.x * TPB + tid;
    const int gstride = GRID * TPB;

    // ---- phase 0: init scratch + repack decoder weights ----
    for (int i = gt; i < NN; i += gstride) { g_deg[i] = 1.0f; g_slot1[i] = -1; g_slot2[i] = -1; }
    for (int l = gt; l < D3 * H3; l += gstride) {
        int r = l / H3, c = l - r * H3;
        g_wihT[c * D3 + r] = dWih[l];
    }
    for (int l = gt; l < 3 * 3 * 48 * H3; l += gstride) {
        int o = l % H3;
        int j = (l / H3) % 48;
        int p = (l / (H3 * 48)) % 3;
        int ct = l / (H3 * 48 * 3);
        g_wdecR[l] = dWhh[(ct * H3 + o) * H3 + (p * 48 + j)];
    }
    if (gt == 0) { g_s1cnt = 0; g_n1 = 0; g_s2ecnt = 0; g_n2 = 0; }
    grid_bar();

    // ---- phase A: collect in-edges of node 0 (no degree atomics) ----
    for (int e4 = gt; e4 < EE / 4; e4 += gstride) {
        int4 c = reinterpret_cast<const int4*>(ei + EE)[e4];
        if (c.x == 0 || c.y == 0 || c.z == 0 || c.w == 0) {
            int4 r = reinterpret_cast<const int4*>(ei)[e4];
            float4 w = reinterpret_cast<const float4*>(ew)[e4];
            if (c.x == 0) { int p = atomicAdd(&g_s1cnt, 1); if (p < CAP1) { g_s1rows[p] = r.x; g_s1w[p] = w.x; } }
            if (c.y == 0) { int p = atomicAdd(&g_s1cnt, 1); if (p < CAP1) { g_s1rows[p] = r.y; g_s1w[p] = w.y; } }
            if (c.z == 0) { int p = atomicAdd(&g_s1cnt, 1); if (p < CAP1) { g_s1rows[p] = r.z; g_s1w[p] = w.z; } }
            if (c.w == 0) { int p = atomicAdd(&g_s1cnt, 1); if (p < CAP1) { g_s1rows[p] = r.w; g_s1w[p] = w.w; } }
        }
    }
    grid_bar();

    // ---- phase S1: build S1 slot table (block 0 only) ----
    if (blockIdx.x == 0) {
        int n = min(g_s1cnt, CAP1);
        for (int i = tid; i <= n; i += TPB) {
            int v = (i == n) ? 0 : g_s1rows[i];
            if (atomicCAS(&g_slot1[v], -1, -2) == -1) {
                int s = atomicAdd(&g_n1, 1);
                if (s < CAP1) g_s1nodes[s] = v;
                g_slot1[v] = s;
            }
            if (atomicCAS(&g_slot2[v], -1, -2) == -1) {
                int s = atomicAdd(&g_n2, 1);
                if (s < MAX2) g_s2nodes[s] = v;
                g_slot2[v] = s;
            }
        }
    }
    grid_bar();

    // ---- phase B: collect in-edges of S1; register source rows in S2 ----
    for (int e4 = gt; e4 < EE / 4; e4 += gstride) {
        int4 c = reinterpret_cast<const int4*>(ei + EE)[e4];
        bool hx = g_slot1[c.x] >= 0, hy = g_slot1[c.y] >= 0,
             hz = g_slot1[c.z] >= 0, hw = g_slot1[c.w] >= 0;
        if (hx || hy || hz || hw) {
            int4 r = reinterpret_cast<const int4*>(ei)[e4];
            float4 w = reinterpret_cast<const float4*>(ew)[e4];
            int cc[4] = {c.x, c.y, c.z, c.w};
            int rr[4] = {r.x, r.y, r.z, r.w};
            float ww[4] = {w.x, w.y, w.z, w.w};
            bool hh[4] = {hx, hy, hz, hw};
            #pragma unroll
            for (int q = 0; q < 4; q++) {
                if (!hh[q]) continue;
                int pos = atomicAdd(&g_s2ecnt, 1);
                if (pos < CAPE) { g_s2erow[pos] = rr[q]; g_s2ecol[pos] = cc[q]; g_s2ew[pos] = ww[q]; }
                if (atomicCAS(&g_slot2[rr[q]], -1, -2) == -1) {
                    int s = atomicAdd(&g_n2, 1);
                    if (s < MAX2) g_s2nodes[s] = rr[q];
                    g_slot2[rr[q]] = s;
                }
            }
        }
    }
    grid_bar();

    // ---- phase C: degrees only at S2 nodes ----
    for (int e4 = gt; e4 < EE / 4; e4 += gstride) {
        int4 c = reinterpret_cast<const int4*>(ei + EE)[e4];
        bool hx = g_slot2[c.x] >= 0, hy = g_slot2[c.y] >= 0,
             hz = g_slot2[c.z] >= 0, hw = g_slot2[c.w] >= 0;
        if (hx || hy || hz || hw) {
            float4 w = reinterpret_cast<const float4*>(ew)[e4];
            if (hx) atomicAdd(&g_deg[c.x], w.x);
            if (hy) atomicAdd(&g_deg[c.y], w.y);
            if (hz) atomicAdd(&g_deg[c.z], w.z);
            if (hw) atomicAdd(&g_deg[c.w], w.w);
        }
    }
    grid_bar();

    // ---- phase GRU ----
    if (blockIdx.x == 0) {
        gru_seq(past, TPAST, cpw, cpb, pWih, pWhh, pbih, pbhh,
                sh.gru.xs, sh.gru.xe, sh.gru.ga, sh.gru.gb, sh.gru.h);
        if (tid < HK) g_target[tid] = sh.gru.h[tid];
    } else if (blockIdx.x == 1) {
        gru_seq(future, TFUT, cfw, cfb, fWih, fWhh, fbih, fbhh,
                sh.gru.xs, sh.gru.xe, sh.gru.ga, sh.gru.gb, sh.gru.h);
        if (tid < HK) g_futv[tid] = sh.gru.h[tid];
    } else {
        int n2 = min(g_n2, MAX2);
        for (int i = blockIdx.x - 2; i < n2; i += GRID - 2) {
            int node = g_s2nodes[i];
            gru_seq(x + (size_t)node * (2 * TPAST), TPAST, cpw, cpb, pWih, pWhh, pbih, pbhh,
                    sh.gru.xs, sh.gru.xe, sh.gru.ga, sh.gru.gb, sh.gru.h);
            if (tid < HK) {
                float acc = 0.f;
                #pragma unroll
                for (int j = 0; j < HK; j++) acc += sh.gru.h[j] * g1w[tid * HK + j];
                g_xw1[i * HK + tid] = acc;
            }
            __syncthreads();
        }
    }
    grid_bar();

    // ---- phase L: GCN layer1 + layer2 at node 0 (block 0, shared memory) ----
    if (blockIdx.x == 0) {
        int n1 = min(g_n1, SLOTS);
        for (int i = tid; i < n1 * HK; i += TPB) sh.lyr.acc[i] = 0.f;
        for (int i = tid; i < n1; i += TPB) sh.lyr.coef[i] = 0.f;
        __syncthreads();
        int ne = min(g_s2ecnt, CAPE);
        for (int idx = tid; idx < ne * HK; idx += TPB) {
            int e = idx / HK, k = idx - e * HK;
            int row = g_s2erow[e], col = g_s2ecol[e];
            float norm = rsqrtf(g_deg[row]) * g_s2ew[e] * rsqrtf(g_deg[col]);
            int s2 = g_slot2[row];
            int s1 = g_slot1[col];
            if (s1 >= 0 && s1 < n1 && s2 >= 0 && s2 < MAX2)
                atomicAdd(&sh.lyr.acc[s1 * HK + k], g_xw1[s2 * HK + k] * norm);
        }
        __syncthreads();
        // finalize layer 1: self term + bias + relu (in place)
        for (int idx = tid; idx < n1 * HK; idx += TPB) {
            int s = idx / HK, k = idx - s * HK;
            int v = g_s1nodes[s];
            float self = g_xw1[g_slot2[v] * HK + k] / g_deg[v];
            sh.lyr.acc[idx] = fmaxf(sh.lyr.acc[idx] + self + g1b[k], 0.f);
        }
        __syncthreads();
        // layer 2 coefficients
        int ncnt = min(g_s1cnt, CAP1);
        float d0 = rsqrtf(g_deg[0]);
        for (int i = tid; i < ncnt; i += TPB) {
            int row = g_s1rows[i];
            float nrm = rsqrtf(g_deg[row]) * g_s1w[i] * d0;
            int s = g_slot1[row];
            if (s >= 0 && s < n1) atomicAdd(&sh.lyr.coef[s], nrm);
        }
        __syncthreads();
        if (tid == 0) sh.lyr.coef[g_slot1[0]] += 1.0f / g_deg[0];
        __syncthreads();
        if (tid < HK) {
            float a = 0.f;
            for (int s = 0; s < n1; s++) a += sh.lyr.coef[s] * sh.lyr.acc[s * HK + tid];
            sh.lyr.xagg[tid] = a;
        }
        __syncthreads();
        if (tid < HK) {
            float a = g2b[tid];
            #pragma unroll
            for (int j = 0; j < HK; j++) a += sh.lyr.xagg[j] * g2w[tid * HK + j];
            g_interact[tid] = a;
        }
    }
}

// ---------------- decoder: 3-CTA cluster, Whh slice in registers ----------------
__device__ __forceinline__ unsigned smem_u32(const void* p) {
    return (unsigned)__cvta_generic_to_shared(p);
}
__device__ __forceinline__ void st_remote_f32(unsigned laddr, unsigned rank, float v) {
    unsigned r;
    asm volatile("mapa.shared::cluster.u32 %0, %1, %2;" : "=r"(r) : "r"(laddr), "r"(rank));
    asm volatile("st.shared::cluster.f32 [%0], %1;" :: "r"(r), "f"(v) : "memory");
}
__device__ __forceinline__ void cluster_sync_() {
    asm volatile("barrier.cluster.arrive.aligned;" ::: "memory");
    asm volatile("barrier.cluster.wait.aligned;" ::: "memory");
}
__device__ __forceinline__ unsigned ctarank_() {
    unsigned r; asm("mov.u32 %0, %%cluster_ctarank;" : "=r"(r)); return r;
}

__global__ __launch_bounds__(432, 1) __cluster_dims__(3, 1, 1)
void k_decoder(const float* __restrict__ past,
               const float* __restrict__ dbih, const float* __restrict__ dbhh,
               const float* __restrict__ fcw, const float* __restrict__ fcb,
               float* __restrict__ out) {
    __shared__ float sc[H3];
    __shared__ float sga0[D3];
    __shared__ float sbih[D3], sbhh[D3];
    __shared__ float h[H3];
    __shared__ float part[432];
    __shared__ float gates[2][D3];
    __shared__ float pres[2];
    int tid = threadIdx.x;
    unsigned ct = ctarank_();
    int o = tid % H3, p = tid / H3;

    float w[48];
    {
        const float* wbase = g_wdecR + ((ct * 3 + p) * 48) * H3 + o;
        #pragma unroll
        for (int j = 0; j < 48; j++) w[j] = wbase[j * H3];
    }
    if (tid < HK) { sc[tid] = g_interact[tid]; sc[HK + tid] = g_target[tid]; sc[2 * HK + tid] = g_futv[tid]; }
    if (tid < D3) { sbih[tid] = dbih[tid]; sbhh[tid] = dbhh[tid]; }
    if (tid < H3) h[tid] = 0.f;
    if (tid < 2) pres[tid] = past[(TPAST - 1) * 2 + tid];
    __syncthreads();

    // step-0 gi: row gr = ct*144+o, partial over input dims j in [48p, 48p+48)
    {
        float a0 = 0.f, a1 = 0.f;
        int gr = ct * H3 + o;
        const float* wt = g_wihT + gr;
        int j0 = p * 48;
        #pragma unroll
        for (int j = j0; j < j0 + 48; j += 2) {
            a0 += wt[j * D3] * sc[j];
            a1 += wt[(j + 1) * D3] * sc[j + 1];
        }
        part[tid] = a0 + a1;
    }
    __syncthreads();
    if (tid < H3) {
        int gi = ct * H3 + tid;
        float v = part[tid] + part[tid + H3] + part[tid + 2 * H3] + sbih[gi];
        sga0[gi] = v;
        unsigned laddr = smem_u32(&sga0[gi]);
        st_remote_f32(laddr, (ct + 1) % 3, v);
        st_remote_f32(laddr, (ct + 2) % 3, v);
    }
    __syncthreads();

    for (int i = 0; i < TFUT; i++) {
        {
            float a0 = 0.f, a1 = 0.f;
            const float* hp = &h[p * 48];
            #pragma unroll
            for (int j = 0; j < 48; j += 2) {
                a0 += w[j] * hp[j];
                a1 += w[j + 1] * hp[j + 1];
            }
            part[tid] = a0 + a1;
        }
        __syncthreads();
        int buf = i & 1;
        if (tid < H3) {
            int gi = ct * H3 + tid;
            float g = part[tid] + part[tid + H3] + part[tid + 2 * H3] + sbhh[gi];
            gates[buf][gi] = g;
            unsigned laddr = smem_u32(&gates[buf][gi]);
            st_remote_f32(laddr, (ct + 1) % 3, g);
            st_remote_f32(laddr, (ct + 2) % 3, g);
        }
        cluster_sync_();
        if (tid < H3) {
            float gar = i ? sbih[tid]          : sga0[tid];
            float gaz = i ? sbih[H3 + tid]     : sga0[H3 + tid];
            float gan = i ? sbih[2 * H3 + tid] : sga0[2 * H3 + tid];
            float r = sigmoidf(gar + gates[buf][tid]);
            float z = sigmoidf(gaz + gates[buf][H3 + tid]);
            float n = tanhf(gan + r * gates[buf][2 * H3 + tid]);
            h[tid] = (1.f - z) * n + z * h[tid];
        }
        __syncthreads();
        if (ct == 0 && tid < 64) {
            int d = tid >> 5, lane = tid & 31;
            float a = 0.f;
            for (int j = lane; j < H3; j += 32) a += h[j] * fcw[d * H3 + j];
            #pragma unroll
            for (int off = 16; off; off >>= 1) a += __shfl_down_sync(0xffffffffu, a, off);
            if (lane == 0) { pres[d] += a + fcb[d]; out[i * 2 + d] = pres[d]; }
        }
        __syncthreads();
    }
}

// ---------------- launch ----------------
extern "C" void kernel_launch(void* const* d_in, const int* in_sizes, int n_in,
                              void* d_out, int out_size) {
    (void)in_sizes; (void)n_in; (void)out_size;
    const float* past   = (const float*)d_in[0];
    const float* future = (const float*)d_in[1];
    const float* x      = (const float*)d_in[2];
    const int*   ei     = (const int*)  d_in[3];
    const float* ew     = (const float*)d_in[4];
    const float* cpw  = (const float*)d_in[5];
    const float* cpb  = (const float*)d_in[6];
    const float* cfw  = (const float*)d_in[7];
    const float* cfb  = (const float*)d_in[8];
    const float* pWih = (const float*)d_in[9];
    const float* pWhh = (const float*)d_in[10];
    const float* pbih = (const float*)d_in[11];
    const float* pbhh = (const float*)d_in[12];
    const float* fWih = (const float*)d_in[13];
    const float* fWhh = (const float*)d_in[14];
    const float* fbih = (const float*)d_in[15];
    const float* fbhh = (const float*)d_in[16];
    const float* dWih = (const float*)d_in[17];
    const float* dWhh = (const float*)d_in[18];
    const float* dbih = (const float*)d_in[19];
    const float* dbhh = (const float*)d_in[20];
    const float* fcw  = (const float*)d_in[21];
    const float* fcb  = (const float*)d_in[22];
    const float* g1w  = (const float*)d_in[23];
    const float* g1b  = (const float*)d_in[24];
    const float* g2w  = (const float*)d_in[25];
    const float* g2b  = (const float*)d_in[26];
    float* out = (float*)d_out;

    k_main<<<GRID, TPB>>>(x, past, future, ei, ew,
                          cpw, cpb, cfw, cfb,
                          pWih, pWhh, pbih, pbhh,
                          fWih, fWhh, fbih, fbhh,
                          g1w, g1b, g2w, g2b, dWih, dWhh);
    k_decoder<<<3, 432>>>(past, dbih, dbhh, fcw, fcb, out);
}

// round 5
// speedup vs baseline: 1.6384x; 1.6384x over previous
#include <cuda_runtime.h>
#include <math.h>

// Problem constants
#define NN    65536
#define EE    1048576
#define TPAST 20
#define TFUT  40
#define HK    48
#define H3    144
#define D3    432

#define CAP1  4096
#define CAPE  65536
#define MAX2  70000

// ---------------- device scratch ----------------
__device__ float g_deg[NN];
__device__ int   g_slot1[NN];
__device__ int   g_slot2[NN];
__device__ int   g_s1rows[CAP1];
__device__ float g_s1w[CAP1];
__device__ int   g_s1nodes[CAP1];
__device__ int   g_s2erow[CAPE];
__device__ int   g_s2ecol[CAPE];
__device__ float g_s2ew[CAPE];
__device__ int   g_s2nodes[MAX2];
__device__ float g_xw1[MAX2 * HK];
__device__ float g_x1acc[CAP1 * HK];
__device__ float g_x1[CAP1 * HK];
__device__ float g_interact[HK];
__device__ float g_target[HK];
__device__ float g_futv[HK];
// decoder Whh, register-slice layout for h-dim partitioning:
// addr = ((ct*3 + p)*48 + j)*H3 + rl ; value = Whh[grow(ct,rl)][48p + j]
// grow(ct, rl) = (rl/48)*144 + ct*48 + (rl%48)
__device__ float g_wdecR[3 * 3 * 48 * H3];
__device__ float g_wihT[H3 * D3];           // dec_Wih (432x144) transposed [c*D3 + r]
__device__ int g_s1cnt, g_n1, g_s2ecnt, g_n2;

__device__ __forceinline__ float sigmoidf(float x) { return 1.0f / (1.0f + expf(-x)); }

// ---------------- prep ----------------
__global__ void k_prep(const float* __restrict__ Whh, const float* __restrict__ Wih) {
    int stride = gridDim.x * blockDim.x;
    int t0 = blockIdx.x * blockDim.x + threadIdx.x;
    for (int i = t0; i < NN; i += stride) { g_deg[i] = 1.0f; g_slot1[i] = -1; g_slot2[i] = -1; }
    for (int i = t0; i < CAP1 * HK; i += stride) g_x1acc[i] = 0.f;
    for (int l = t0; l < D3 * H3; l += stride) {
        int r = l / H3, c = l - r * H3;
        g_wihT[c * D3 + r] = Wih[l];
    }
    for (int l = t0; l < 3 * 3 * 48 * H3; l += stride) {
        int rl = l % H3;
        int j = (l / H3) % 48;
        int p = (l / (H3 * 48)) % 3;
        int ct = l / (H3 * 48 * 3);
        int grow = (rl / 48) * H3 + ct * 48 + (rl % 48);
        g_wdecR[l] = Whh[grow * H3 + (p * 48 + j)];
    }
    if (t0 == 0) { g_s1cnt = 0; g_n1 = 0; g_s2ecnt = 0; g_n2 = 0; }
}

// ---------------- edge passes ----------------
__global__ void k_passA(const int* __restrict__ ei, const float* __restrict__ ew) {
    int e4 = blockIdx.x * blockDim.x + threadIdx.x;
    if (e4 * 4 >= EE) return;
    int4 c = reinterpret_cast<const int4*>(ei + EE)[e4];
    float4 w = reinterpret_cast<const float4*>(ew)[e4];
    atomicAdd(&g_deg[c.x], w.x);
    atomicAdd(&g_deg[c.y], w.y);
    atomicAdd(&g_deg[c.z], w.z);
    atomicAdd(&g_deg[c.w], w.w);
    if (c.x == 0 || c.y == 0 || c.z == 0 || c.w == 0) {
        int4 r = reinterpret_cast<const int4*>(ei)[e4];
        if (c.x == 0) { int pos = atomicAdd(&g_s1cnt, 1); if (pos < CAP1) { g_s1rows[pos] = r.x; g_s1w[pos] = w.x; } }
        if (c.y == 0) { int pos = atomicAdd(&g_s1cnt, 1); if (pos < CAP1) { g_s1rows[pos] = r.y; g_s1w[pos] = w.y; } }
        if (c.z == 0) { int pos = atomicAdd(&g_s1cnt, 1); if (pos < CAP1) { g_s1rows[pos] = r.z; g_s1w[pos] = w.z; } }
        if (c.w == 0) { int pos = atomicAdd(&g_s1cnt, 1); if (pos < CAP1) { g_s1rows[pos] = r.w; g_s1w[pos] = w.w; } }
    }
}

__global__ void k_s1nodes() {
    int n = min(g_s1cnt, CAP1);
    for (int i = threadIdx.x; i <= n; i += blockDim.x) {
        int v = (i == n) ? 0 : g_s1rows[i];
        if (atomicCAS(&g_slot1[v], -1, -2) == -1) {
            int s = atomicAdd(&g_n1, 1);
            if (s < CAP1) g_s1nodes[s] = v;
            g_slot1[v] = s;
        }
        if (atomicCAS(&g_slot2[v], -1, -2) == -1) {
            int s = atomicAdd(&g_n2, 1);
            if (s < MAX2) g_s2nodes[s] = v;
            g_slot2[v] = s;
        }
    }
}

__device__ __forceinline__ void passB_one(int col, int row, float w) {
    if (g_slot1[col] >= 0) {
        int pos = atomicAdd(&g_s2ecnt, 1);
        if (pos < CAPE) { g_s2erow[pos] = row; g_s2ecol[pos] = col; g_s2ew[pos] = w; }
        if (atomicCAS(&g_slot2[row], -1, -2) == -1) {
            int s = atomicAdd(&g_n2, 1);
            if (s < MAX2) g_s2nodes[s] = row;
            g_slot2[row] = s;
        }
    }
}

__global__ void k_passB(const int* __restrict__ ei, const float* __restrict__ ew) {
    int e4 = blockIdx.x * blockDim.x + threadIdx.x;
    if (e4 * 4 >= EE) return;
    int4 c = reinterpret_cast<const int4*>(ei + EE)[e4];
    int4 r = reinterpret_cast<const int4*>(ei)[e4];
    float4 w = reinterpret_cast<const float4*>(ew)[e4];
    passB_one(c.x, r.x, w.x);
    passB_one(c.y, r.y, w.y);
    passB_one(c.z, r.z, w.z);
    passB_one(c.w, r.w, w.w);
}

// ---------------- conv1d+GRU sequence (per-block) ----------------
__device__ void gru_seq(const float* __restrict__ xin, int T,
                        const float* __restrict__ cw, const float* __restrict__ cb,
                        const float* __restrict__ Wih, const float* __restrict__ Whh,
                        const float* __restrict__ bih, const float* __restrict__ bhh,
                        float* xs, float* xe, float* ga, float* gb, float* h) {
    int tid = threadIdx.x;
    for (int i = tid; i < 2 * T; i += blockDim.x) xs[i] = xin[i];
    if (tid < HK) h[tid] = 0.f;
    __syncthreads();
    for (int idx = tid; idx < T * HK; idx += blockDim.x) {
        int t = idx / HK, k = idx - t * HK;
        float acc = cb[k];
        #pragma unroll
        for (int j = 0; j < 3; j++) {
            int tt = t + j - 1;
            if (tt >= 0 && tt < T)
                acc += xs[tt * 2 + 0] * cw[(k * 2 + 0) * 3 + j]
                     + xs[tt * 2 + 1] * cw[(k * 2 + 1) * 3 + j];
        }
        xe[idx] = fmaxf(acc, 0.f);
    }
    float wi[HK], wh[HK];
    float bi = 0.f, bh = 0.f;
    if (tid < H3) {
        #pragma unroll
        for (int j = 0; j < HK; j++) { wi[j] = Wih[tid * HK + j]; wh[j] = Whh[tid * HK + j]; }
        bi = bih[tid]; bh = bhh[tid];
    }
    __syncthreads();
    for (int t = 0; t < T; t++) {
        if (tid < H3) {
            float a0 = bi, a1 = 0.f, b0 = bh, b1 = 0.f;
            const float* xt = &xe[t * HK];
            #pragma unroll
            for (int j = 0; j < HK; j += 2) {
                a0 += wi[j] * xt[j];     a1 += wi[j + 1] * xt[j + 1];
                b0 += wh[j] * h[j];      b1 += wh[j + 1] * h[j + 1];
            }
            ga[tid] = a0 + a1; gb[tid] = b0 + b1;
        }
        __syncthreads();
        float hn = 0.f;
        if (tid < HK) {
            float r = sigmoidf(ga[tid] + gb[tid]);
            float z = sigmoidf(ga[HK + tid] + gb[HK + tid]);
            float n = tanhf(ga[2 * HK + tid] + r * gb[2 * HK + tid]);
            hn = (1.f - z) * n + z * h[tid];
        }
        __syncthreads();
        if (tid < HK) h[tid] = hn;
        __syncthreads();
    }
}

__global__ __launch_bounds__(160) void k_gru_all(
    const float* __restrict__ x,
    const float* __restrict__ past, const float* __restrict__ future,
    const float* __restrict__ cpw, const float* __restrict__ cpb,
    const float* __restrict__ cfw, const float* __restrict__ cfb,
    const float* __restrict__ pWih, const float* __restrict__ pWhh,
    const float* __restrict__ pbih, const float* __restrict__ pbhh,
    const float* __restrict__ fWih, const float* __restrict__ fWhh,
    const float* __restrict__ fbih, const float* __restrict__ fbhh,
    const float* __restrict__ g1w) {
    __shared__ float xs[2 * TFUT], xe[TFUT * HK], ga[H3], gb[H3], h[HK];
    if (blockIdx.x == 0) {
        gru_seq(past, TPAST, cpw, cpb, pWih, pWhh, pbih, pbhh, xs, xe, ga, gb, h);
        if (threadIdx.x < HK) g_target[threadIdx.x] = h[threadIdx.x];
        return;
    }
    if (blockIdx.x == 1) {
        gru_seq(future, TFUT, cfw, cfb, fWih, fWhh, fbih, fbhh, xs, xe, ga, gb, h);
        if (threadIdx.x < HK) g_futv[threadIdx.x] = h[threadIdx.x];
        return;
    }
    int n2 = min(g_n2, MAX2);
    for (int i = blockIdx.x - 2; i < n2; i += gridDim.x - 2) {
        int node = g_s2nodes[i];
        gru_seq(x + (size_t)node * (2 * TPAST), TPAST, cpw, cpb, pWih, pWhh, pbih, pbhh,
                xs, xe, ga, gb, h);
        if (threadIdx.x < HK) {
            float acc = 0.f;
            #pragma unroll
            for (int j = 0; j < HK; j++) acc += h[j] * g1w[threadIdx.x * HK + j];
            g_xw1[i * HK + threadIdx.x] = acc;
        }
        __syncthreads();
    }
}

// ---------------- GCN cone ----------------
__global__ void k_layer1() {
    int ne = min(g_s2ecnt, CAPE);
    int total = ne * HK;
    int stride = gridDim.x * blockDim.x;
    for (int idx = blockIdx.x * blockDim.x + threadIdx.x; idx < total; idx += stride) {
        int e = idx / HK, k = idx - e * HK;
        int row = g_s2erow[e], col = g_s2ecol[e];
        float norm = rsqrtf(g_deg[row]) * g_s2ew[e] * rsqrtf(g_deg[col]);
        int s2 = g_slot2[row];
        int s1 = g_slot1[col];
        if (s2 >= 0 && s2 < MAX2 && s1 >= 0 && s1 < CAP1)
            atomicAdd(&g_x1acc[s1 * HK + k], g_xw1[s2 * HK + k] * norm);
    }
}

__global__ void k_layer2(const float* __restrict__ b1,
                         const float* __restrict__ g2w, const float* __restrict__ g2b) {
    __shared__ float coef[1024];
    __shared__ float xagg[HK];
    int tid = threadIdx.x;
    int n1 = min(g_n1, CAP1);
    for (int idx = tid; idx < n1 * HK; idx += blockDim.x) {
        int s = idx / HK, k = idx - s * HK;
        int v = g_s1nodes[s];
        float self = g_xw1[g_slot2[v] * HK + k] / g_deg[v];
        g_x1[idx] = fmaxf(g_x1acc[idx] + self + b1[k], 0.f);
    }
    int n1c = min(n1, 1024);
    int ncnt = min(g_s1cnt, CAP1);
    for (int i = tid; i < n1c; i += blockDim.x) coef[i] = 0.f;
    __syncthreads();
    float d0 = rsqrtf(g_deg[0]);
    for (int i = tid; i < ncnt; i += blockDim.x) {
        int row = g_s1rows[i];
        float nrm = rsqrtf(g_deg[row]) * g_s1w[i] * d0;
        int s = g_slot1[row];
        if (s >= 0 && s < n1c) atomicAdd(&coef[s], nrm);
    }
    __syncthreads();
    if (tid == 0) coef[g_slot1[0]] += 1.0f / g_deg[0];
    __syncthreads();
    if (tid < HK) {
        float a = 0.f;
        for (int s = 0; s < n1c; s++) a += coef[s] * g_x1[s * HK + tid];
        xagg[tid] = a;
    }
    __syncthreads();
    if (tid < HK) {
        float a = g2b[tid];
        #pragma unroll
        for (int j = 0; j < HK; j++) a += xagg[j] * g2w[tid * HK + j];
        g_interact[tid] = a;
    }
}

// ---------------- decoder: h-dim partitioned, st.async + mbarrier sync ----------------
__device__ __forceinline__ unsigned smem_u32(const void* p) {
    return (unsigned)__cvta_generic_to_shared(p);
}
__device__ __forceinline__ unsigned ctarank_() {
    unsigned r; asm("mov.u32 %0, %%cluster_ctarank;" : "=r"(r)); return r;
}
__device__ __forceinline__ void mbar_init(unsigned mbar, unsigned cnt) {
    asm volatile("mbarrier.init.shared.b64 [%0], %1;" :: "r"(mbar), "r"(cnt) : "memory");
}
__device__ __forceinline__ void mbar_arrive_expect(unsigned mbar, unsigned bytes) {
    asm volatile("mbarrier.arrive.expect_tx.shared.b64 _, [%0], %1;"
                 :: "r"(mbar), "r"(bytes) : "memory");
}
__device__ __forceinline__ void mbar_wait(unsigned mbar, unsigned phase) {
    asm volatile(
        "{\n\t.reg .pred P;\n\t"
        "WL_%=:\n\t"
        "mbarrier.try_wait.parity.shared.b64 P, [%0], %1;\n\t"
        "@!P bra WL_%=;\n\t}"
        :: "r"(mbar), "r"(phase) : "memory");
}
__device__ __forceinline__ void st_async_f32(unsigned raddr, float v, unsigned rmbar) {
    asm volatile("st.async.shared::cluster.mbarrier::complete_tx::bytes.f32 [%0], %1, [%2];"
                 :: "r"(raddr), "f"(v), "r"(rmbar) : "memory");
}
__device__ __forceinline__ unsigned mapa_(unsigned laddr, unsigned rank) {
    unsigned r;
    asm volatile("mapa.shared::cluster.u32 %0, %1, %2;" : "=r"(r) : "r"(laddr), "r"(rank));
    return r;
}

__global__ __launch_bounds__(432, 1) __cluster_dims__(3, 1, 1)
void k_decoder(const float* __restrict__ past,
               const float* __restrict__ dbih, const float* __restrict__ dbhh,
               const float* __restrict__ fcw, const float* __restrict__ fcb,
               float* __restrict__ out) {
    __shared__ float hbuf[2][H3];
    __shared__ float part[432];
    __shared__ float gbl[H3];
    __shared__ float ga0[H3];
    __shared__ float sbihL[H3], sbhhL[H3];
    __shared__ float sc[H3];
    __shared__ float sfcw[2 * H3];
    __shared__ float pres[2];
    __shared__ __align__(8) unsigned long long mbs[2];

    int tid = threadIdx.x;
    unsigned ct = ctarank_();
    int rl = tid % H3, p = tid / H3;
    // global gate row for local row rl: gate (rl/48), h-dim ct*48 + rl%48
    int grow = (rl / 48) * H3 + (int)ct * 48 + (rl % 48);

    unsigned mb0 = smem_u32(&mbs[0]), mb1 = smem_u32(&mbs[1]);
    if (tid == 0) { mbar_init(mb0, 1); mbar_init(mb1, 1); }

    // register-resident Whh slice: 48 weights per thread
    float w[48];
    {
        const float* wbase = g_wdecR + (((int)ct * 3 + p) * 48) * H3 + rl;
        #pragma unroll
        for (int j = 0; j < 48; j++) w[j] = wbase[j * H3];
    }
    if (tid < HK) { sc[tid] = g_interact[tid]; sc[HK + tid] = g_target[tid]; sc[2 * HK + tid] = g_futv[tid]; }
    if (tid < H3) { hbuf[0][tid] = 0.f; sbihL[tid] = dbih[grow]; sbhhL[tid] = dbhh[grow]; }
    if (ct == 0) {
        if (tid < 2 * H3) sfcw[tid] = fcw[tid];
        if (tid < 2) pres[tid] = past[(TPAST - 1) * 2 + tid];
    }
    __syncthreads();

    // step-0 gi partial: row grow, input cols [48p, 48p+48)
    {
        float a = 0.f;
        const float* wt = g_wihT + grow;
        #pragma unroll
        for (int j = 0; j < 48; j++) a += wt[(p * 48 + j) * D3] * sc[p * 48 + j];
        part[tid] = a;
    }
    __syncthreads();
    if (tid < H3) ga0[tid] = part[tid] + part[tid + H3] + part[tid + 2 * H3] + sbihL[tid];
    __syncthreads();
    // cluster-wide: mbarrier inits + hbuf[0] visible before any st.async
    asm volatile("barrier.cluster.arrive.aligned;" ::: "memory");
    asm volatile("barrier.cluster.wait.aligned;" ::: "memory");

    int base = (int)ct * 48;
    for (int i = 0; i < TFUT; i++) {
        int cur = i & 1, bi = cur ^ 1;
        unsigned mbar = bi ? mb1 : mb0;
        unsigned ph = (i >> 1) & 1;
        // matvec partial: gate rows of this CTA, h cols [48p, 48p+48)
        {
            float a0 = 0.f, a1 = 0.f;
            const float* hp = &hbuf[cur][p * 48];
            #pragma unroll
            for (int j = 0; j < 48; j += 2) {
                a0 += w[j] * hp[j];
                a1 += w[j + 1] * hp[j + 1];
            }
            part[tid] = a0 + a1;
        }
        __syncthreads();
        if (tid < H3) gbl[tid] = part[tid] + part[tid + H3] + part[tid + 2 * H3] + sbhhL[tid];
        __syncthreads();
        if (tid < 48) {
            float gar = i ? sbihL[tid]      : ga0[tid];
            float gaz = i ? sbihL[48 + tid] : ga0[48 + tid];
            float gan = i ? sbihL[96 + tid] : ga0[96 + tid];
            float r = sigmoidf(gar + gbl[tid]);
            float z = sigmoidf(gaz + gbl[48 + tid]);
            float n = tanhf(gan + r * gbl[96 + tid]);
            float hn = (1.f - z) * n + z * hbuf[cur][base + tid];
            hbuf[bi][base + tid] = hn;
            unsigned la = smem_u32(&hbuf[bi][base + tid]);
            st_async_f32(mapa_(la, (ct + 1) % 3), hn, mapa_(mbar, (ct + 1) % 3));
            st_async_f32(mapa_(la, (ct + 2) % 3), hn, mapa_(mbar, (ct + 2) % 3));
        }
        if (tid == 0) mbar_arrive_expect(mbar, 384);  // 2 peers x 48 floats
        __syncthreads();
        mbar_wait(mbar, ph);
        if (ct == 0 && tid < 64) {
            int d = tid >> 5, lane = tid & 31;
            float a = 0.f;
            #pragma unroll
            for (int j = lane; j < H3; j += 32) a += hbuf[bi][j] * sfcw[d * H3 + j];
            #pragma unroll
            for (int off = 16; off; off >>= 1) a += __shfl_down_sync(0xffffffffu, a, off);
            if (lane == 0) { pres[d] += a + fcb[d]; out[i * 2 + d] = pres[d]; }
        }
    }
}

// ---------------- launch ----------------
extern "C" void kernel_launch(void* const* d_in, const int* in_sizes, int n_in,
                              void* d_out, int out_size) {
    (void)in_sizes; (void)n_in; (void)out_size;
    const float* past   = (const float*)d_in[0];
    const float* future = (const float*)d_in[1];
    const float* x      = (const float*)d_in[2];
    const int*   ei     = (const int*)  d_in[3];
    const float* ew     = (const float*)d_in[4];
    const float* cpw  = (const float*)d_in[5];
    const float* cpb  = (const float*)d_in[6];
    const float* cfw  = (const float*)d_in[7];
    const float* cfb  = (const float*)d_in[8];
    const float* pWih = (const float*)d_in[9];
    const float* pWhh = (const float*)d_in[10];
    const float* pbih = (const float*)d_in[11];
    const float* pbhh = (const float*)d_in[12];
    const float* fWih = (const float*)d_in[13];
    const float* fWhh = (const float*)d_in[14];
    const float* fbih = (const float*)d_in[15];
    const float* fbhh = (const float*)d_in[16];
    const float* dWih = (const float*)d_in[17];
    const float* dWhh = (const float*)d_in[18];
    const float* dbih = (const float*)d_in[19];
    const float* dbhh = (const float*)d_in[20];
    const float* fcw  = (const float*)d_in[21];
    const float* fcb  = (const float*)d_in[22];
    const float* g1w  = (const float*)d_in[23];
    const float* g1b  = (const float*)d_in[24];
    const float* g2w  = (const float*)d_in[25];
    const float* g2b  = (const float*)d_in[26];
    float* out = (float*)d_out;

    k_prep<<<1024, 256>>>(dWhh, dWih);
    k_passA<<<EE / 4 / 256, 256>>>(ei, ew);
    k_s1nodes<<<1, 256>>>();
    k_passB<<<EE / 4 / 256, 256>>>(ei, ew);
    k_gru_all<<<1026, 160>>>(x, past, future, cpw, cpb, cfw, cfb,
                             pWih, pWhh, pbih, pbhh, fWih, fWhh, fbih, fbhh, g1w);
    k_layer1<<<64, 256>>>();
    k_layer2<<<1, 256>>>(g1b, g2w, g2b);
    k_decoder<<<3, 432>>>(past, dbih, dbhh, fcw, fcb, out);
}